// round 1
// baseline (speedup 1.0000x reference)
#include <cuda_runtime.h>
#include <math.h>

#define BZ   512
#define TM1  127
#define ENC  256
#define HS   256      // LSTM hidden
#define NBLK 128      // persistent LSTM grid

// ---------------- device state ----------------
__device__ float g_wenc[ENC];
__device__ float g_dT[HS][BZ];          // d hidden state, transposed [h][b]
__device__ float g_ytilde[TM1][BZ];     // per-step scalar LSTM input * precomputed
__device__ float g_ctxfin[BZ];          // context · W_final[256:512]
__device__ unsigned g_bar_count;
__device__ volatile unsigned g_bar_gen;

// ---------------- kernel A: fused attention weight + barrier init ----------------
__global__ void k_prep(const float* __restrict__ W_attn1,
                       const float* __restrict__ W_attn2) {
    int j = threadIdx.x;            // 0..255
    float acc = 0.f;
    #pragma unroll 4
    for (int k = 0; k < 128; ++k)
        acc += W_attn2[k] * W_attn1[k * 768 + 512 + j];
    g_wenc[j] = acc;
    if (j == 0) { g_bar_count = 0; g_bar_gen = 0; }
}

// ---------------- kernel B: scores -> softmax -> context -> folded dots ----------------
__global__ void k_attn(const float* __restrict__ X,
                       const float* __restrict__ y_prev,
                       const float* __restrict__ W_fc,
                       const float* __restrict__ b_fc,
                       const float* __restrict__ W_final) {
    __shared__ float wenc_s[256];
    __shared__ float sc[128];
    __shared__ float red[256];
    __shared__ float red2[256];
    const int b   = blockIdx.x;
    const int tid = threadIdx.x;
    const int lane = tid & 31, warp = tid >> 5;
    wenc_s[tid] = g_wenc[tid];
    __syncthreads();

    const float* Xb = X + (size_t)b * TM1 * ENC;

    // scores: one warp per row group
    for (int t = warp; t < TM1; t += 8) {
        const float* xr = Xb + t * ENC;
        float p = 0.f;
        #pragma unroll
        for (int i = 0; i < 8; ++i)
            p += xr[lane + 32 * i] * wenc_s[lane + 32 * i];
        #pragma unroll
        for (int o = 16; o; o >>= 1) p += __shfl_down_sync(0xffffffffu, p, o);
        if (lane == 0) sc[t] = p;
    }
    __syncthreads();

    // softmax over 127
    float v = (tid < TM1) ? sc[tid] : -INFINITY;
    red[tid] = v; __syncthreads();
    for (int s = 128; s; s >>= 1) {
        if (tid < s) red[tid] = fmaxf(red[tid], red[tid + s]);
        __syncthreads();
    }
    float m = red[0];
    __syncthreads();
    float e = (tid < TM1) ? __expf(v - m) : 0.f;
    red[tid] = e; __syncthreads();
    for (int s = 128; s; s >>= 1) {
        if (tid < s) red[tid] += red[tid + s];
        __syncthreads();
    }
    float inv = 1.f / red[0];
    __syncthreads();
    if (tid < TM1) sc[tid] = e * inv;
    __syncthreads();

    // context[e] = sum_t beta[t] * X[b,t,e]; fold into the 2 dots that consume it
    float ctx = 0.f;
    #pragma unroll 4
    for (int t = 0; t < TM1; ++t)
        ctx += sc[t] * Xb[t * ENC + tid];

    red[tid]  = ctx * W_fc[tid];
    red2[tid] = ctx * W_final[256 + tid];
    __syncthreads();
    for (int s = 128; s; s >>= 1) {
        if (tid < s) { red[tid] += red[tid + s]; red2[tid] += red2[tid + s]; }
        __syncthreads();
    }
    float ytc = red[0] + b_fc[0];           // context·W_fc[:256] + b_fc
    if (tid == 0) g_ctxfin[b] = red2[0];

    const float wfy = W_fc[256];
    for (int t = tid; t < TM1; t += 256)
        g_ytilde[t][b] = ytc + y_prev[b * TM1 + t] * wfy;
}

// ---------------- persistent LSTM ----------------
__device__ __forceinline__ void grid_barrier() {
    __syncthreads();
    if (threadIdx.x == 0) {
        __threadfence();
        unsigned gen = g_bar_gen;
        if (atomicAdd(&g_bar_count, 1u) == NBLK - 1) {
            g_bar_count = 0;
            __threadfence();
            g_bar_gen = gen + 1;
        } else {
            while (g_bar_gen == gen) __nanosleep(64);
        }
    }
    __syncthreads();
}

__device__ __forceinline__ float sigmoidf(float x) {
    return 1.f / (1.f + __expf(-x));
}

// block tile: 64 batches x 16 h (x4 gates). thread: 4 batches x 1 h (4 gates).
// smem: W rows [k][r] (r = tx*4+g) and d tile [k][b_local], row stride 68.
__global__ void __launch_bounds__(256, 1) k_lstm(
    const float* __restrict__ W_hh, const float* __restrict__ W_ih,
    const float* __restrict__ b_ih, const float* __restrict__ b_hh)
{
    extern __shared__ float smem[];
    float* w_s = smem;              // [256][68]
    float* d_s = smem + 256 * 68;   // [256][68]

    const int tid = threadIdx.x;
    const int tx = tid & 15;        // h within tile
    const int ty = tid >> 4;        // batch group (4 each)
    const int b_tile = blockIdx.x & 7;
    const int h_tile = blockIdx.x >> 3;
    const int h      = h_tile * 16 + tx;
    const int b_base = b_tile * 64;
    const int b_thr  = b_base + ty * 4;

    // ---- preload W_hh tile (transposed, stays in smem for all 127 steps) ----
    for (int idx = tid; idx < 64 * 64; idx += 256) {
        int r  = idx >> 6;          // 0..63 = local row: h' = r>>2, gate = r&3
        int k4 = idx & 63;
        int g  = r & 3;
        int hh = h_tile * 16 + (r >> 2);
        float4 wv = *reinterpret_cast<const float4*>(W_hh + (size_t)(g * 256 + hh) * 256 + k4 * 4);
        w_s[(k4 * 4 + 0) * 68 + r] = wv.x;
        w_s[(k4 * 4 + 1) * 68 + r] = wv.y;
        w_s[(k4 * 4 + 2) * 68 + r] = wv.z;
        w_s[(k4 * 4 + 3) * 68 + r] = wv.w;
    }

    float wih[4], bias[4];
    #pragma unroll
    for (int g = 0; g < 4; ++g) {
        int j = g * 256 + h;
        wih[g]  = W_ih[j];
        bias[g] = b_ih[j] + b_hh[j];
    }

    // zero my slice of d, c lives in registers
    *reinterpret_cast<float4*>(&g_dT[h][b_thr]) = make_float4(0.f, 0.f, 0.f, 0.f);
    float c_reg[4] = {0.f, 0.f, 0.f, 0.f};

    grid_barrier();

    const float* dp = d_s + ty * 4;
    const float* wp = w_s + tx * 4;

    for (int t = 0; t < TM1; ++t) {
        // load d tile [256 k][64 b] (cross-SM data -> bypass L1)
        for (int i = tid; i < 256 * 16; i += 256) {
            int k = i >> 4, c = i & 15;
            float4 dv = __ldcg(reinterpret_cast<const float4*>(&g_dT[k][b_base + c * 4]));
            *reinterpret_cast<float4*>(&d_s[k * 68 + c * 4]) = dv;
        }
        __syncthreads();

        float4 yt = *reinterpret_cast<const float4*>(&g_ytilde[t][b_thr]);
        float ytv[4] = {yt.x, yt.y, yt.z, yt.w};
        float acc[4][4];
        #pragma unroll
        for (int bb = 0; bb < 4; ++bb)
            #pragma unroll
            for (int g = 0; g < 4; ++g)
                acc[bb][g] = ytv[bb] * wih[g] + bias[g];

        #pragma unroll 8
        for (int k = 0; k < 256; ++k) {
            float4 dv = *reinterpret_cast<const float4*>(dp + k * 68);
            float4 wv = *reinterpret_cast<const float4*>(wp + k * 68);
            acc[0][0] += dv.x * wv.x; acc[0][1] += dv.x * wv.y;
            acc[0][2] += dv.x * wv.z; acc[0][3] += dv.x * wv.w;
            acc[1][0] += dv.y * wv.x; acc[1][1] += dv.y * wv.y;
            acc[1][2] += dv.y * wv.z; acc[1][3] += dv.y * wv.w;
            acc[2][0] += dv.z * wv.x; acc[2][1] += dv.z * wv.y;
            acc[2][2] += dv.z * wv.z; acc[2][3] += dv.z * wv.w;
            acc[3][0] += dv.w * wv.x; acc[3][1] += dv.w * wv.y;
            acc[3][2] += dv.w * wv.z; acc[3][3] += dv.w * wv.w;
        }

        float4 dnew;
        float* dn = &dnew.x;
        #pragma unroll
        for (int bb = 0; bb < 4; ++bb) {
            float ig = sigmoidf(acc[bb][0]);
            float fg = sigmoidf(acc[bb][1]);
            float gg = tanhf(acc[bb][2]);
            float og = sigmoidf(acc[bb][3]);
            float cn = fg * c_reg[bb] + ig * gg;
            c_reg[bb] = cn;
            dn[bb] = og * tanhf(cn);
        }
        *reinterpret_cast<float4*>(&g_dT[h][b_thr]) = dnew;

        grid_barrier();
    }
}

// ---------------- final projection ----------------
__global__ void k_final(const float* __restrict__ W_final,
                        const float* __restrict__ b_final,
                        float* __restrict__ out) {
    int b = blockIdx.x * 8 + (threadIdx.x >> 5);
    int lane = threadIdx.x & 31;
    float acc = 0.f;
    #pragma unroll
    for (int i = 0; i < 8; ++i) {
        int hh = lane + 32 * i;
        acc += g_dT[hh][b] * W_final[hh];
    }
    #pragma unroll
    for (int o = 16; o; o >>= 1) acc += __shfl_down_sync(0xffffffffu, acc, o);
    if (lane == 0) out[b] = acc + g_ctxfin[b] + b_final[0];
}

// ---------------- launch ----------------
extern "C" void kernel_launch(void* const* d_in, const int* in_sizes, int n_in,
                              void* d_out, int out_size) {
    const float* X       = (const float*)d_in[0];
    const float* y_prev  = (const float*)d_in[1];
    const float* W_attn1 = (const float*)d_in[2];
    const float* W_attn2 = (const float*)d_in[4];
    const float* W_fc    = (const float*)d_in[6];
    const float* b_fc    = (const float*)d_in[7];
    const float* W_ih    = (const float*)d_in[8];
    const float* W_hh    = (const float*)d_in[9];
    const float* b_ih    = (const float*)d_in[10];
    const float* b_hh    = (const float*)d_in[11];
    const float* W_final = (const float*)d_in[12];
    const float* b_final = (const float*)d_in[13];
    float* out = (float*)d_out;

    const int smem_bytes = 2 * 256 * 68 * sizeof(float);   // 139264
    cudaFuncSetAttribute(k_lstm, cudaFuncAttributeMaxDynamicSharedMemorySize, smem_bytes);

    k_prep<<<1, 256>>>(W_attn1, W_attn2);
    k_attn<<<BZ, 256>>>(X, y_prev, W_fc, b_fc, W_final);
    k_lstm<<<NBLK, 256, smem_bytes>>>(W_hh, W_ih, b_ih, b_hh);
    k_final<<<BZ / 8, 256>>>(W_final, b_final, out);
}

// round 2
// speedup vs baseline: 1.5648x; 1.5648x over previous
#include <cuda_runtime.h>
#include <math.h>

#define BZ   512
#define TM1  127
#define ENC  256
#define HS   256      // LSTM hidden
#define NBLK 128      // persistent LSTM grid

// ---------------- device state ----------------
__device__ float g_wenc[ENC];
__device__ float g_dT[HS][BZ];          // d hidden state, transposed [h][b]
__device__ float g_ytilde[TM1][BZ];     // per-step scalar LSTM input * precomputed
__device__ float g_ctxfin[BZ];          // context · W_final[256:512]
__device__ unsigned g_bar_count;
__device__ volatile unsigned g_bar_gen;

// ---------------- kernel A: fused attention weight + barrier init ----------------
__global__ void k_prep(const float* __restrict__ W_attn1,
                       const float* __restrict__ W_attn2) {
    int j = threadIdx.x;            // 0..255
    float acc = 0.f;
    #pragma unroll 4
    for (int k = 0; k < 128; ++k)
        acc += W_attn2[k] * W_attn1[k * 768 + 512 + j];
    g_wenc[j] = acc;
    if (j == 0) { g_bar_count = 0; g_bar_gen = 0; }
}

// ---------------- kernel B: scores -> softmax -> context -> folded dots ----------------
__global__ void k_attn(const float* __restrict__ X,
                       const float* __restrict__ y_prev,
                       const float* __restrict__ W_fc,
                       const float* __restrict__ b_fc,
                       const float* __restrict__ W_final) {
    __shared__ float wenc_s[256];
    __shared__ float sc[128];
    __shared__ float red[256];
    __shared__ float red2[256];
    const int b   = blockIdx.x;
    const int tid = threadIdx.x;
    const int lane = tid & 31, warp = tid >> 5;
    wenc_s[tid] = g_wenc[tid];
    __syncthreads();

    const float* Xb = X + (size_t)b * TM1 * ENC;

    // scores: one warp per row group
    for (int t = warp; t < TM1; t += 8) {
        const float* xr = Xb + t * ENC;
        float p = 0.f;
        #pragma unroll
        for (int i = 0; i < 8; ++i)
            p += xr[lane + 32 * i] * wenc_s[lane + 32 * i];
        #pragma unroll
        for (int o = 16; o; o >>= 1) p += __shfl_down_sync(0xffffffffu, p, o);
        if (lane == 0) sc[t] = p;
    }
    __syncthreads();

    // softmax over 127
    float v = (tid < TM1) ? sc[tid] : -INFINITY;
    red[tid] = v; __syncthreads();
    for (int s = 128; s; s >>= 1) {
        if (tid < s) red[tid] = fmaxf(red[tid], red[tid + s]);
        __syncthreads();
    }
    float m = red[0];
    __syncthreads();
    float e = (tid < TM1) ? __expf(v - m) : 0.f;
    red[tid] = e; __syncthreads();
    for (int s = 128; s; s >>= 1) {
        if (tid < s) red[tid] += red[tid + s];
        __syncthreads();
    }
    float inv = 1.f / red[0];
    __syncthreads();
    if (tid < TM1) sc[tid] = e * inv;
    __syncthreads();

    // context[e] = sum_t beta[t] * X[b,t,e]; fold into the 2 dots that consume it
    float ctx = 0.f;
    #pragma unroll 4
    for (int t = 0; t < TM1; ++t)
        ctx += sc[t] * Xb[t * ENC + tid];

    red[tid]  = ctx * W_fc[tid];
    red2[tid] = ctx * W_final[256 + tid];
    __syncthreads();
    for (int s = 128; s; s >>= 1) {
        if (tid < s) { red[tid] += red[tid + s]; red2[tid] += red2[tid + s]; }
        __syncthreads();
    }
    float ytc = red[0] + b_fc[0];           // context·W_fc[:256] + b_fc
    if (tid == 0) g_ctxfin[b] = red2[0];

    const float wfy = W_fc[256];
    for (int t = tid; t < TM1; t += 256)
        g_ytilde[t][b] = ytc + y_prev[b * TM1 + t] * wfy;
}

// ---------------- persistent LSTM ----------------
__device__ __forceinline__ void grid_barrier() {
    __syncthreads();
    if (threadIdx.x == 0) {
        __threadfence();
        unsigned gen = g_bar_gen;
        if (atomicAdd(&g_bar_count, 1u) == NBLK - 1) {
            g_bar_count = 0;
            __threadfence();
            g_bar_gen = gen + 1;
        } else {
            while (g_bar_gen == gen) __nanosleep(64);
        }
    }
    __syncthreads();
}

__device__ __forceinline__ float sigmoidf(float x) {
    return 1.f / (1.f + __expf(-x));
}

// block tile: 64 batches x 16 h (x4 gates). thread: 4 batches x 1 h (4 gates).
// smem: W rows [k][r] (r = tx*4+g) and d tile [k][b_local], row stride 68.
__global__ void __launch_bounds__(256, 1) k_lstm(
    const float* __restrict__ W_hh, const float* __restrict__ W_ih,
    const float* __restrict__ b_ih, const float* __restrict__ b_hh)
{
    extern __shared__ float smem[];
    float* w_s = smem;              // [256][68]
    float* d_s = smem + 256 * 68;   // [256][68]

    const int tid = threadIdx.x;
    const int tx = tid & 15;        // h within tile
    const int ty = tid >> 4;        // batch group (4 each)
    const int b_tile = blockIdx.x & 7;
    const int h_tile = blockIdx.x >> 3;
    const int h      = h_tile * 16 + tx;
    const int b_base = b_tile * 64;
    const int b_thr  = b_base + ty * 4;

    // ---- preload W_hh tile (transposed, stays in smem for all 127 steps) ----
    for (int idx = tid; idx < 64 * 64; idx += 256) {
        int r  = idx >> 6;          // 0..63 = local row: h' = r>>2, gate = r&3
        int k4 = idx & 63;
        int g  = r & 3;
        int hh = h_tile * 16 + (r >> 2);
        float4 wv = *reinterpret_cast<const float4*>(W_hh + (size_t)(g * 256 + hh) * 256 + k4 * 4);
        w_s[(k4 * 4 + 0) * 68 + r] = wv.x;
        w_s[(k4 * 4 + 1) * 68 + r] = wv.y;
        w_s[(k4 * 4 + 2) * 68 + r] = wv.z;
        w_s[(k4 * 4 + 3) * 68 + r] = wv.w;
    }

    float wih[4], bias[4];
    #pragma unroll
    for (int g = 0; g < 4; ++g) {
        int j = g * 256 + h;
        wih[g]  = W_ih[j];
        bias[g] = b_ih[j] + b_hh[j];
    }

    // zero my slice of d, c lives in registers
    *reinterpret_cast<float4*>(&g_dT[h][b_thr]) = make_float4(0.f, 0.f, 0.f, 0.f);
    float c_reg[4] = {0.f, 0.f, 0.f, 0.f};

    grid_barrier();

    const float* dp = d_s + ty * 4;
    const float* wp = w_s + tx * 4;

    for (int t = 0; t < TM1; ++t) {
        // load d tile [256 k][64 b] (cross-SM data -> bypass L1)
        for (int i = tid; i < 256 * 16; i += 256) {
            int k = i >> 4, c = i & 15;
            float4 dv = __ldcg(reinterpret_cast<const float4*>(&g_dT[k][b_base + c * 4]));
            *reinterpret_cast<float4*>(&d_s[k * 68 + c * 4]) = dv;
        }
        __syncthreads();

        float4 yt = *reinterpret_cast<const float4*>(&g_ytilde[t][b_thr]);
        float ytv[4] = {yt.x, yt.y, yt.z, yt.w};
        float acc[4][4];
        #pragma unroll
        for (int bb = 0; bb < 4; ++bb)
            #pragma unroll
            for (int g = 0; g < 4; ++g)
                acc[bb][g] = ytv[bb] * wih[g] + bias[g];

        #pragma unroll 8
        for (int k = 0; k < 256; ++k) {
            float4 dv = *reinterpret_cast<const float4*>(dp + k * 68);
            float4 wv = *reinterpret_cast<const float4*>(wp + k * 68);
            acc[0][0] += dv.x * wv.x; acc[0][1] += dv.x * wv.y;
            acc[0][2] += dv.x * wv.z; acc[0][3] += dv.x * wv.w;
            acc[1][0] += dv.y * wv.x; acc[1][1] += dv.y * wv.y;
            acc[1][2] += dv.y * wv.z; acc[1][3] += dv.y * wv.w;
            acc[2][0] += dv.z * wv.x; acc[2][1] += dv.z * wv.y;
            acc[2][2] += dv.z * wv.z; acc[2][3] += dv.z * wv.w;
            acc[3][0] += dv.w * wv.x; acc[3][1] += dv.w * wv.y;
            acc[3][2] += dv.w * wv.z; acc[3][3] += dv.w * wv.w;
        }

        float4 dnew;
        float* dn = &dnew.x;
        #pragma unroll
        for (int bb = 0; bb < 4; ++bb) {
            float ig = sigmoidf(acc[bb][0]);
            float fg = sigmoidf(acc[bb][1]);
            float gg = tanhf(acc[bb][2]);
            float og = sigmoidf(acc[bb][3]);
            float cn = fg * c_reg[bb] + ig * gg;
            c_reg[bb] = cn;
            dn[bb] = og * tanhf(cn);
        }
        *reinterpret_cast<float4*>(&g_dT[h][b_thr]) = dnew;

        grid_barrier();
    }
}

// ---------------- final projection ----------------
__global__ void k_final(const float* __restrict__ W_final,
                        const float* __restrict__ b_final,
                        float* __restrict__ out) {
    int b = blockIdx.x * 8 + (threadIdx.x >> 5);
    int lane = threadIdx.x & 31;
    float acc = 0.f;
    #pragma unroll
    for (int i = 0; i < 8; ++i) {
        int hh = lane + 32 * i;
        acc += g_dT[hh][b] * W_final[hh];
    }
    #pragma unroll
    for (int o = 16; o; o >>= 1) acc += __shfl_down_sync(0xffffffffu, acc, o);
    if (lane == 0) out[b] = acc + g_ctxfin[b] + b_final[0];
}

// ---------------- launch ----------------
extern "C" void kernel_launch(void* const* d_in, const int* in_sizes, int n_in,
                              void* d_out, int out_size) {
    const float* X       = (const float*)d_in[0];
    const float* y_prev  = (const float*)d_in[1];
    const float* W_attn1 = (const float*)d_in[2];
    const float* W_attn2 = (const float*)d_in[4];
    const float* W_fc    = (const float*)d_in[6];
    const float* b_fc    = (const float*)d_in[7];
    const float* W_ih    = (const float*)d_in[8];
    const float* W_hh    = (const float*)d_in[9];
    const float* b_ih    = (const float*)d_in[10];
    const float* b_hh    = (const float*)d_in[11];
    const float* W_final = (const float*)d_in[12];
    const float* b_final = (const float*)d_in[13];
    float* out = (float*)d_out;

    const int smem_bytes = 2 * 256 * 68 * sizeof(float);   // 139264
    cudaFuncSetAttribute(k_lstm, cudaFuncAttributeMaxDynamicSharedMemorySize, smem_bytes);

    k_prep<<<1, 256>>>(W_attn1, W_attn2);
    k_attn<<<BZ, 256>>>(X, y_prev, W_fc, b_fc, W_final);
    k_lstm<<<NBLK, 256, smem_bytes>>>(W_hh, W_ih, b_ih, b_hh);
    k_final<<<BZ / 8, 256>>>(W_final, b_final, out);
}